// round 2
// baseline (speedup 1.0000x reference)
#include <cuda_runtime.h>
#include <float.h>

#define NN   8192   // nodes per graph
#define DF   128    // feature dim
#define NA   512    // anchors
#define KSEL 32     // top-K
#define TA   32     // anchors per CTA tile
#define TN   128    // nodes per CTA tile
#define DC   32     // d chunk

// Scratch (allocation-free rule: __device__ globals)
__device__ float g_dist[2][NA][NN];   // 32MB distance matrices
__device__ float g_D[NA];             // margin-augmented positive distances

// ---------------------------------------------------------------------------
// Kernel A: D[a] = L1(out1[anchor1[a]], out2[anchor2[a]]) + MARGIN; zero d_out
// One warp per anchor; lane handles one float4 (4 dims), 32 lanes * 4 = 128.
// ---------------------------------------------------------------------------
__global__ __launch_bounds__(256) void prep_kernel(
    const float* __restrict__ out1, const float* __restrict__ out2,
    const int* __restrict__ anchor1, const int* __restrict__ anchor2,
    float* out)
{
    int tid  = blockIdx.x * blockDim.x + threadIdx.x;
    if (tid == 0) out[0] = 0.0f;          // d_out is poisoned; zero it for atomics
    int a    = tid >> 5;
    int lane = tid & 31;
    if (a >= NA) return;
    const float4* r1 = (const float4*)(out1 + (size_t)anchor1[a] * DF);
    const float4* r2 = (const float4*)(out2 + (size_t)anchor2[a] * DF);
    float4 v1 = r1[lane];
    float4 v2 = r2[lane];
    float s = fabsf(v1.x - v2.x) + fabsf(v1.y - v2.y)
            + fabsf(v1.z - v2.z) + fabsf(v1.w - v2.w);
    #pragma unroll
    for (int o = 16; o; o >>= 1) s += __shfl_xor_sync(0xffffffffu, s, o);
    if (lane == 0) g_D[a] = s + 1.0f;
}

// ---------------------------------------------------------------------------
// Kernel B: tiled L1 cdist.  dir 0: A = out1[anchor1], B = out2
//                            dir 1: A = out2[anchor2], B = out1
// CTA tile: 32 anchors x 128 nodes, full d=128 (chunked by 32 for B).
// Both tiles stored d-major in smem -> inner loop: 1 broadcast LDS.128 (A)
// + 1 coalesced LDS.128 (B) per d-step feeding a 4x4 |a-b| micro-tile.
// ---------------------------------------------------------------------------
__global__ __launch_bounds__(256) void dist_kernel(
    const float* __restrict__ out1, const float* __restrict__ out2,
    const int* __restrict__ anchor1, const int* __restrict__ anchor2)
{
    __shared__ __align__(16) float Ast[DF][36];      // [d][anchor], padded
    __shared__ __align__(16) float Bs[DC][TN + 4];   // [d][node], padded

    int dir = blockIdx.z;
    const float* Asrc = dir ? out2 : out1;
    const float* Bsrc = dir ? out1 : out2;
    const int*   anc  = dir ? anchor2 : anchor1;
    int a_base = blockIdx.y * TA;
    int n_base = blockIdx.x * TN;
    int tid  = threadIdx.x;

    // Load + transpose A tile: 32 anchor rows x 128 d
    {
        int a  = tid >> 3;        // 0..31
        int dq = tid & 7;         // float4 index within a 32-d chunk
        const float4* src = (const float4*)(Asrc + (size_t)anc[a_base + a] * DF);
        #pragma unroll
        for (int c = 0; c < 4; c++) {
            float4 v = src[dq + 8 * c];
            int d = (dq << 2) + (c << 5);
            Ast[d + 0][a] = v.x; Ast[d + 1][a] = v.y;
            Ast[d + 2][a] = v.z; Ast[d + 3][a] = v.w;
        }
    }

    int warp = tid >> 5, lane = tid & 31;
    int a0 = warp << 2;           // 8 warps x 4 anchors = 32
    int n0 = lane << 2;           // 32 lanes x 4 nodes  = 128

    float acc[4][4];
    #pragma unroll
    for (int i = 0; i < 4; i++)
        #pragma unroll
        for (int j = 0; j < 4; j++) acc[i][j] = 0.0f;

    for (int dc = 0; dc < DF; dc += DC) {
        __syncthreads();   // protects Bs reuse (and Ast stores on first pass)
        // Load + transpose B chunk: 128 node rows x 32 d
        #pragma unroll
        for (int p = 0; p < 4; p++) {
            int l  = (p << 8) + tid;     // 0..1023 float4s
            int n  = l >> 3;
            int dq = l & 7;
            float4 v = *(const float4*)(Bsrc + (size_t)(n_base + n) * DF + dc + (dq << 2));
            int d = dq << 2;
            Bs[d + 0][n] = v.x; Bs[d + 1][n] = v.y;
            Bs[d + 2][n] = v.z; Bs[d + 3][n] = v.w;
        }
        __syncthreads();
        #pragma unroll
        for (int dd = 0; dd < DC; dd++) {
            float4 av = *(const float4*)&Ast[dc + dd][a0];   // warp-broadcast
            float4 bv = *(const float4*)&Bs[dd][n0];         // conflict-free
            float aa[4] = {av.x, av.y, av.z, av.w};
            float bb[4] = {bv.x, bv.y, bv.z, bv.w};
            #pragma unroll
            for (int i = 0; i < 4; i++)
                #pragma unroll
                for (int j = 0; j < 4; j++)
                    acc[i][j] += fabsf(aa[i] - bb[j]);
        }
    }

    #pragma unroll
    for (int i = 0; i < 4; i++) {
        float4 w = make_float4(acc[i][0], acc[i][1], acc[i][2], acc[i][3]);
        *(float4*)&g_dist[dir][a_base + a0 + i][n_base + n0] = w;  // coalesced
    }
}

// ---------------------------------------------------------------------------
// Kernel C: per row, sum relu(D - d_k) over the 32 smallest of 8192 distances.
// Cached-min scheme: each thread owns 32 strided smem slots and a cached
// (min, slot); per iteration we reduce cached mins, the single winner
// invalidates + rescans, everyone else reuses the cache.
// ---------------------------------------------------------------------------
__global__ __launch_bounds__(256) void select_kernel(float* out)
{
    __shared__ float vals[NN];            // 32KB
    __shared__ float wmin[8];
    __shared__ int   wwho[8];
    __shared__ int   s_who;

    int row = blockIdx.x;                 // 0..1023
    int dir = row >> 9;
    int a   = row & (NA - 1);
    int tid = threadIdx.x;
    int lane = tid & 31, warp = tid >> 5;

    const float* src = g_dist[dir][a];
    for (int i = tid; i < NN; i += 256) vals[i] = src[i];
    __syncthreads();

    float cmin = FLT_MAX; int cidx = 0;
    #pragma unroll
    for (int i = 0; i < 32; i++) {
        float v = vals[i * 256 + tid];    // conflict-free strided ownership
        if (v < cmin) { cmin = v; cidx = i; }
    }

    float D = g_D[a];
    float lsum = 0.0f;

    for (int k = 0; k < KSEL; k++) {
        float m = cmin; int who = tid;
        #pragma unroll
        for (int o = 16; o; o >>= 1) {
            float om = __shfl_xor_sync(0xffffffffu, m, o);
            int   ow = __shfl_xor_sync(0xffffffffu, who, o);
            if (om < m) { m = om; who = ow; }
        }
        if (lane == 0) { wmin[warp] = m; wwho[warp] = who; }
        __syncthreads();
        if (tid == 0) {
            float bm = wmin[0]; int bw = wwho[0];
            #pragma unroll
            for (int w = 1; w < 8; w++)
                if (wmin[w] < bm) { bm = wmin[w]; bw = wwho[w]; }
            s_who = bw;
            lsum += fmaxf(D - bm, 0.0f);
        }
        __syncthreads();
        if (tid == s_who) {               // only the winner rescans its 32 slots
            vals[cidx * 256 + tid] = FLT_MAX;
            cmin = FLT_MAX; cidx = 0;
            #pragma unroll
            for (int i = 0; i < 32; i++) {
                float v = vals[i * 256 + tid];
                if (v < cmin) { cmin = v; cidx = i; }
            }
        }
        // no trailing sync needed: next iter's barrier orders s_who/wmin reuse
    }
    if (tid == 0) atomicAdd(out, lsum * (1.0f / (NA * KSEL)));
}

// ---------------------------------------------------------------------------
extern "C" void kernel_launch(void* const* d_in, const int* in_sizes, int n_in,
                              void* d_out, int out_size)
{
    const float* out1    = (const float*)d_in[0];
    const float* out2    = (const float*)d_in[1];
    const int*   anchor1 = (const int*)d_in[2];
    const int*   anchor2 = (const int*)d_in[3];
    float* out = (float*)d_out;

    prep_kernel<<<64, 256>>>(out1, out2, anchor1, anchor2, out);

    dim3 grid(NN / TN, NA / TA, 2);   // 64 x 16 x 2
    dist_kernel<<<grid, 256>>>(out1, out2, anchor1, anchor2);

    select_kernel<<<2 * NA, 256>>>(out);
}